// round 16
// baseline (speedup 1.0000x reference)
#include <cuda_runtime.h>

// Bilinear 2x upsample, half_pixel_centers=False (asymmetric: h = hd/2).
// Input : (16, 64, 128, 128) fp32, Output: (16, 64, 256, 256) fp32.
//
// FINAL KERNEL — measured optimum, reproduced 4x (bench 55.296/55.456/
// 55.328/55.296 us; kernel 50.0-50.7 us; rel_err 0.0). Evidence R5-R15:
//  - store path (STG / __stcs / __stwt / 32KB cp.async.bulk): identical perf
//  - tile size (1 / 2 / 4 rows per warp): 50.5 / 50.2 / 52.0 us kernel
//  - occupancy 55-79%: no effect
// => path/policy/occupancy-independent ~5.5TB/s pure-write HBM wall;
// kernel runs within ~3% of the 268.4MB compulsory-write traffic floor.
//
// Stencil (exact, neighbors clamped at 127):
//   out[2i  ][2j  ] = x[i][j]
//   out[2i  ][2j+1] = (x[i][j] + x[i][j+1]) / 2
//   odd output rows = average of adjacent even-row expansions (H is linear)
//
// One warp per input ROW PAIR (2r, 2r+1): loads rows 2r, 2r+1, 2r+2 (clamped)
// via 6 coalesced 256B float2 warp loads, emits output rows 4r..4r+3 via 8
// fully-coalesced 512B float4 warp stores (each = 4 exact cache lines).

static constexpr int SRC_H = 128;
static constexpr int SRC_W = 128;
static constexpr int NC    = 16 * 64;   // 1024
static constexpr int DST_W = 256;

struct RowData {
    float2 v0, v1;   // cols (2l, 2l+1) and (64+2l, 64+2l+1)
    float  n0, n1;   // right neighbors: cols 2l+2 and 64+2l+2 (clamped)
};

__device__ __forceinline__ void h_expand(const RowData& r, float4& e0, float4& e1) {
    e0 = make_float4(r.v0.x, 0.5f * (r.v0.x + r.v0.y),
                     r.v0.y, 0.5f * (r.v0.y + r.n0));
    e1 = make_float4(r.v1.x, 0.5f * (r.v1.x + r.v1.y),
                     r.v1.y, 0.5f * (r.v1.y + r.n1));
}

__device__ __forceinline__ float4 avg4(const float4& a, const float4& b) {
    return make_float4(0.5f * (a.x + b.x), 0.5f * (a.y + b.y),
                       0.5f * (a.z + b.z), 0.5f * (a.w + b.w));
}

__global__ void __launch_bounds__(256)
bilinear2x_kernel(const float* __restrict__ in, float* __restrict__ out) {
    const unsigned F = 0xffffffffu;
    const int warp_global = blockIdx.x * (blockDim.x >> 5) + (threadIdx.x >> 5);
    const int lane = threadIdx.x & 31;

    const int nc = warp_global >> 6;        // / 64 row-pairs per image
    const int r  = warp_global & 63;        // row-pair index
    const int iA = 2 * r;
    const int iB = 2 * r + 1;
    const int iC = (iB < SRC_H - 1) ? (iB + 1) : iB;   // clamp bottom

    const float* img = in + (size_t)nc * (SRC_H * SRC_W);
    const float2* rowA = reinterpret_cast<const float2*>(img + iA * SRC_W);
    const float2* rowB = reinterpret_cast<const float2*>(img + iB * SRC_W);
    const float2* rowC = reinterpret_cast<const float2*>(img + iC * SRC_W);

    // Front-batch all 6 independent coalesced loads (256B warp transactions)
    RowData A, B, C;
    A.v0 = __ldg(rowA + lane);      A.v1 = __ldg(rowA + 32 + lane);
    B.v0 = __ldg(rowB + lane);      B.v1 = __ldg(rowB + 32 + lane);
    C.v0 = __ldg(rowC + lane);      C.v1 = __ldg(rowC + 32 + lane);

    const int nxt = (lane + 1) & 31;

    // Right-neighbor resolution per row:
    //   half 0: lanes 0..30 -> lane+1's v0.x ; lane 31 -> col 64 = lane 0's v1.x
    //   half 1: lanes 0..30 -> lane+1's v1.x ; lane 31 -> clamp to own v1.y
    {
        float s0 = __shfl_sync(F, A.v0.x, nxt);
        float s1 = __shfl_sync(F, A.v1.x, nxt);
        float t  = __shfl_sync(F, A.v1.x, 0);
        A.n0 = (lane == 31) ? t : s0;
        A.n1 = (lane == 31) ? A.v1.y : s1;
    }
    {
        float s0 = __shfl_sync(F, B.v0.x, nxt);
        float s1 = __shfl_sync(F, B.v1.x, nxt);
        float t  = __shfl_sync(F, B.v1.x, 0);
        B.n0 = (lane == 31) ? t : s0;
        B.n1 = (lane == 31) ? B.v1.y : s1;
    }
    {
        float s0 = __shfl_sync(F, C.v0.x, nxt);
        float s1 = __shfl_sync(F, C.v1.x, nxt);
        float t  = __shfl_sync(F, C.v1.x, 0);
        C.n0 = (lane == 31) ? t : s0;
        C.n1 = (lane == 31) ? C.v1.y : s1;
    }

    // Horizontal expansions of the three input rows
    float4 eA0, eA1, eB0, eB1, eC0, eC1;
    h_expand(A, eA0, eA1);
    h_expand(B, eB0, eB1);
    h_expand(C, eC0, eC1);

    float* outImg = out + (size_t)nc * (2 * SRC_H * DST_W);
    float4* o0 = reinterpret_cast<float4*>(outImg + (4 * r + 0) * DST_W);
    float4* o1 = reinterpret_cast<float4*>(outImg + (4 * r + 1) * DST_W);
    float4* o2 = reinterpret_cast<float4*>(outImg + (4 * r + 2) * DST_W);
    float4* o3 = reinterpret_cast<float4*>(outImg + (4 * r + 3) * DST_W);

    // 8 fully-coalesced 512B warp stores; streaming hint (output never re-read)
    __stcs(o0 + lane,      eA0);
    __stcs(o0 + 32 + lane, eA1);
    __stcs(o1 + lane,      avg4(eA0, eB0));
    __stcs(o1 + 32 + lane, avg4(eA1, eB1));
    __stcs(o2 + lane,      eB0);
    __stcs(o2 + 32 + lane, eB1);
    __stcs(o3 + lane,      avg4(eB0, eC0));
    __stcs(o3 + 32 + lane, avg4(eB1, eC1));
}

extern "C" void kernel_launch(void* const* d_in, const int* in_sizes, int n_in,
                              void* d_out, int out_size) {
    const float* x = (const float*)d_in[0];
    float* out = (float*)d_out;

    const int total_warps = NC * (SRC_H / 2);         // 65536 row-pairs
    const int threads = 256;                          // 8 warps/block
    const int blocks = total_warps / (threads / 32);  // 8192

    bilinear2x_kernel<<<blocks, threads>>>(x, out);
}

// round 17
// speedup vs baseline: 1.0006x; 1.0006x over previous
#include <cuda_runtime.h>

// Bilinear 2x upsample, half_pixel_centers=False (asymmetric: h = hd/2).
// Input : (16, 64, 128, 128) fp32, Output: (16, 64, 256, 256) fp32.
//
// FINAL KERNEL — measured optimum, reproduced 5x (bench 55.296/55.456/
// 55.328/55.296/55.328 us, spread 0.3%; kernel 50.0-51.1 us; rel_err 0.0).
// Evidence R5-R16:
//  - store path (STG / __stcs / __stwt / 32KB cp.async.bulk): identical perf
//  - tile size (1 / 2 / 4 rows per warp): 50.5 / 50.2 / 52.0 us kernel
//  - occupancy 55-79%: no effect
// => path/policy/occupancy-independent ~5.5TB/s pure-write HBM wall;
// kernel runs within ~3% of the 268.4MB compulsory-write traffic floor.
//
// Stencil (exact, neighbors clamped at 127):
//   out[2i  ][2j  ] = x[i][j]
//   out[2i  ][2j+1] = (x[i][j] + x[i][j+1]) / 2
//   odd output rows = average of adjacent even-row expansions (H is linear)
//
// One warp per input ROW PAIR (2r, 2r+1): loads rows 2r, 2r+1, 2r+2 (clamped)
// via 6 coalesced 256B float2 warp loads, emits output rows 4r..4r+3 via 8
// fully-coalesced 512B float4 warp stores (each = 4 exact cache lines).

static constexpr int SRC_H = 128;
static constexpr int SRC_W = 128;
static constexpr int NC    = 16 * 64;   // 1024
static constexpr int DST_W = 256;

struct RowData {
    float2 v0, v1;   // cols (2l, 2l+1) and (64+2l, 64+2l+1)
    float  n0, n1;   // right neighbors: cols 2l+2 and 64+2l+2 (clamped)
};

__device__ __forceinline__ void h_expand(const RowData& r, float4& e0, float4& e1) {
    e0 = make_float4(r.v0.x, 0.5f * (r.v0.x + r.v0.y),
                     r.v0.y, 0.5f * (r.v0.y + r.n0));
    e1 = make_float4(r.v1.x, 0.5f * (r.v1.x + r.v1.y),
                     r.v1.y, 0.5f * (r.v1.y + r.n1));
}

__device__ __forceinline__ float4 avg4(const float4& a, const float4& b) {
    return make_float4(0.5f * (a.x + b.x), 0.5f * (a.y + b.y),
                       0.5f * (a.z + b.z), 0.5f * (a.w + b.w));
}

__global__ void __launch_bounds__(256)
bilinear2x_kernel(const float* __restrict__ in, float* __restrict__ out) {
    const unsigned F = 0xffffffffu;
    const int warp_global = blockIdx.x * (blockDim.x >> 5) + (threadIdx.x >> 5);
    const int lane = threadIdx.x & 31;

    const int nc = warp_global >> 6;        // / 64 row-pairs per image
    const int r  = warp_global & 63;        // row-pair index
    const int iA = 2 * r;
    const int iB = 2 * r + 1;
    const int iC = (iB < SRC_H - 1) ? (iB + 1) : iB;   // clamp bottom

    const float* img = in + (size_t)nc * (SRC_H * SRC_W);
    const float2* rowA = reinterpret_cast<const float2*>(img + iA * SRC_W);
    const float2* rowB = reinterpret_cast<const float2*>(img + iB * SRC_W);
    const float2* rowC = reinterpret_cast<const float2*>(img + iC * SRC_W);

    // Front-batch all 6 independent coalesced loads (256B warp transactions)
    RowData A, B, C;
    A.v0 = __ldg(rowA + lane);      A.v1 = __ldg(rowA + 32 + lane);
    B.v0 = __ldg(rowB + lane);      B.v1 = __ldg(rowB + 32 + lane);
    C.v0 = __ldg(rowC + lane);      C.v1 = __ldg(rowC + 32 + lane);

    const int nxt = (lane + 1) & 31;

    // Right-neighbor resolution per row:
    //   half 0: lanes 0..30 -> lane+1's v0.x ; lane 31 -> col 64 = lane 0's v1.x
    //   half 1: lanes 0..30 -> lane+1's v1.x ; lane 31 -> clamp to own v1.y
    {
        float s0 = __shfl_sync(F, A.v0.x, nxt);
        float s1 = __shfl_sync(F, A.v1.x, nxt);
        float t  = __shfl_sync(F, A.v1.x, 0);
        A.n0 = (lane == 31) ? t : s0;
        A.n1 = (lane == 31) ? A.v1.y : s1;
    }
    {
        float s0 = __shfl_sync(F, B.v0.x, nxt);
        float s1 = __shfl_sync(F, B.v1.x, nxt);
        float t  = __shfl_sync(F, B.v1.x, 0);
        B.n0 = (lane == 31) ? t : s0;
        B.n1 = (lane == 31) ? B.v1.y : s1;
    }
    {
        float s0 = __shfl_sync(F, C.v0.x, nxt);
        float s1 = __shfl_sync(F, C.v1.x, nxt);
        float t  = __shfl_sync(F, C.v1.x, 0);
        C.n0 = (lane == 31) ? t : s0;
        C.n1 = (lane == 31) ? C.v1.y : s1;
    }

    // Horizontal expansions of the three input rows
    float4 eA0, eA1, eB0, eB1, eC0, eC1;
    h_expand(A, eA0, eA1);
    h_expand(B, eB0, eB1);
    h_expand(C, eC0, eC1);

    float* outImg = out + (size_t)nc * (2 * SRC_H * DST_W);
    float4* o0 = reinterpret_cast<float4*>(outImg + (4 * r + 0) * DST_W);
    float4* o1 = reinterpret_cast<float4*>(outImg + (4 * r + 1) * DST_W);
    float4* o2 = reinterpret_cast<float4*>(outImg + (4 * r + 2) * DST_W);
    float4* o3 = reinterpret_cast<float4*>(outImg + (4 * r + 3) * DST_W);

    // 8 fully-coalesced 512B warp stores; streaming hint (output never re-read)
    __stcs(o0 + lane,      eA0);
    __stcs(o0 + 32 + lane, eA1);
    __stcs(o1 + lane,      avg4(eA0, eB0));
    __stcs(o1 + 32 + lane, avg4(eA1, eB1));
    __stcs(o2 + lane,      eB0);
    __stcs(o2 + 32 + lane, eB1);
    __stcs(o3 + lane,      avg4(eB0, eC0));
    __stcs(o3 + 32 + lane, avg4(eB1, eC1));
}

extern "C" void kernel_launch(void* const* d_in, const int* in_sizes, int n_in,
                              void* d_out, int out_size) {
    const float* x = (const float*)d_in[0];
    float* out = (float*)d_out;

    const int total_warps = NC * (SRC_H / 2);         // 65536 row-pairs
    const int threads = 256;                          // 8 warps/block
    const int blocks = total_warps / (threads / 32);  // 8192

    bilinear2x_kernel<<<blocks, threads>>>(x, out);
}